// round 7
// baseline (speedup 1.0000x reference)
#include <cuda_runtime.h>
#include <stdint.h>

// Problem constants (verified by round-5 diagnostics)
#define K_F      1024
#define N_ROWS   256          // B*S = 4*64
#define DIM      256
#define F_FACTS  1000000
#define TOPK     128
#define NEG_INFF (-1.0e9f)

// Inputs (confirmed): 0=fact_success(int32 bool), 1=fact_item_idx(int32),
// 2=facts_idx(int32 [F,3]), 3=entity_emb(f32), 4=rel_emb(f32), 5=top_k(=128)
// Output: THIS ROUND'S EXPERIMENT — float32 0.0/1.0 mask [256,1024].

__device__ float g_scores[N_ROWS * K_F];

// ---------------------------------------------------------------------------
// Kernel 1: one warp per fact. Terms bit-match the reference
// (fl32(fl32(s*r)*o), no FMA); accumulate exactly in double; round once.
// ---------------------------------------------------------------------------
__global__ void __launch_bounds__(256)
score_kernel(const int*   __restrict__ success,   // [N*K_F] int32 bool
             const int*   __restrict__ item_idx,  // [N*K_F]
             const int*   __restrict__ facts_idx, // [F,3]
             const float* __restrict__ ent,       // [E,DIM]
             const float* __restrict__ rel)       // [R,DIM]
{
    int gw   = (blockIdx.x * blockDim.x + threadIdx.x) >> 5;  // fact id
    int lane = threadIdx.x & 31;
    if (gw >= N_ROWS * K_F) return;
    if (!success[gw]) return;   // warp-uniform, no divergence

    int fidx = item_idx[gw];
    fidx = min(max(fidx, 0), F_FACTS - 1);

    int t = 0;
    if (lane < 3) t = facts_idx[fidx * 3 + lane];
    int s_i = __shfl_sync(0xffffffffu, t, 0);
    int r_i = __shfl_sync(0xffffffffu, t, 1);
    int o_i = __shfl_sync(0xffffffffu, t, 2);

    const float4* sp = (const float4*)(ent + (size_t)s_i * DIM);
    const float4* rp = (const float4*)(rel + (size_t)r_i * DIM);
    const float4* op = (const float4*)(ent + (size_t)o_i * DIM);

    double acc = 0.0;
#pragma unroll
    for (int i = 0; i < 2; ++i) {
        float4 a = __ldg(&sp[lane + 32 * i]);
        float4 b = __ldg(&rp[lane + 32 * i]);
        float4 c = __ldg(&op[lane + 32 * i]);
        // Exactly jax's elementwise product: two rounded f32 multiplies.
        acc += (double)__fmul_rn(__fmul_rn(a.x, b.x), c.x);
        acc += (double)__fmul_rn(__fmul_rn(a.y, b.y), c.y);
        acc += (double)__fmul_rn(__fmul_rn(a.z, b.z), c.z);
        acc += (double)__fmul_rn(__fmul_rn(a.w, b.w), c.w);
    }
#pragma unroll
    for (int off = 16; off; off >>= 1)
        acc += __shfl_down_sync(0xffffffffu, acc, off);

    if (lane == 0) g_scores[gw] = (float)acc;   // correctly-rounded true sum
}

// Order-preserving float -> uint key (larger float => larger uint)
__device__ __forceinline__ unsigned orderKey(float f) {
    unsigned u = __float_as_uint(f);
    return (u & 0x80000000u) ? ~u : (u | 0x80000000u);
}

// ---------------------------------------------------------------------------
// Kernel 2: one block (256 threads) per row. Exact top-128 keep mask with
// jax.lax.top_k tie semantics (lowest index wins among equal scores).
// OUTPUT: float32 0.0/1.0.
// ---------------------------------------------------------------------------
__global__ void __launch_bounds__(256)
topk_kernel(const int* __restrict__ success,
            float*     __restrict__ out)
{
    __shared__ unsigned keys[K_F];
    __shared__ int s_cnt;

    const int row = blockIdx.x;
    const int tid = threadIdx.x;
    const float* rs = g_scores + row * K_F;
    const int*   su = success  + row * K_F;

    int      myS[4];
    unsigned myK[4];
#pragma unroll
    for (int i = 0; i < 4; ++i) {
        int j = tid + 256 * i;
        int s = su[j];
        myS[i] = s;
        float f = s ? rs[j] : NEG_INFF;
        myK[i] = orderKey(f);
        keys[j] = myK[i];
    }
    __syncthreads();

    // MSB radix select: exact value of the TOPK-th largest key.
    unsigned prefix = 0;
    int remaining = TOPK;
    for (int bit = 31; bit >= 0; --bit) {
        if (tid == 0) s_cnt = 0;
        __syncthreads();
        unsigned p = prefix | (1u << bit);
        int c = 0;
#pragma unroll
        for (int i = 0; i < 4; ++i)
            c += ((myK[i] >> bit) == (p >> bit));
#pragma unroll
        for (int off = 16; off; off >>= 1)
            c += __shfl_down_sync(0xffffffffu, c, off);
        if ((tid & 31) == 0) atomicAdd(&s_cnt, c);
        __syncthreads();
        int cnt = s_cnt;
        if (cnt >= remaining) prefix = p;
        else                  remaining -= cnt;
        __syncthreads();   // protect s_cnt before next-iter reset
    }
    const unsigned T = prefix;

    // Count strictly-greater keys
    if (tid == 0) s_cnt = 0;
    __syncthreads();
    {
        int g = 0;
#pragma unroll
        for (int i = 0; i < 4; ++i) g += (myK[i] > T);
#pragma unroll
        for (int off = 16; off; off >>= 1)
            g += __shfl_down_sync(0xffffffffu, g, off);
        if ((tid & 31) == 0) atomicAdd(&s_cnt, g);
    }
    __syncthreads();
    const int G = s_cnt;
    const int R = TOPK - G;   // ties at T that survive (lowest index first)

#pragma unroll
    for (int i = 0; i < 4; ++i) {
        int j = tid + 256 * i;
        bool keep;
        if (myK[i] > T) {
            keep = true;
        } else if (myK[i] == T) {
            int before = 0;            // rare path: only tied elements scan
            for (int j2 = 0; j2 < j; ++j2) before += (keys[j2] == T);
            keep = (before < R);
        } else {
            keep = false;
        }
        out[row * K_F + j] = (myS[i] && keep) ? 1.0f : 0.0f;
    }
}

// ---------------------------------------------------------------------------
extern "C" void kernel_launch(void* const* d_in, const int* in_sizes, int n_in,
                              void* d_out, int out_size)
{
    const int*   success   = (const int*)  d_in[0];
    const int*   item_idx  = (const int*)  d_in[1];
    const int*   facts_idx = (const int*)  d_in[2];
    const float* ent       = (const float*)d_in[3];
    const float* rel       = (const float*)d_in[4];
    (void)in_sizes; (void)n_in; (void)out_size;   // top_k verified = 128

    // Kernel 1: 262144 facts, one warp each, 8 warps/block -> 32768 blocks
    score_kernel<<<(N_ROWS * K_F) / 8, 256>>>(success, item_idx, facts_idx, ent, rel);

    // Kernel 2: one block per row, float32 output
    topk_kernel<<<N_ROWS, 256>>>(success, (float*)d_out);
}

// round 8
// speedup vs baseline: 1.1875x; 1.1875x over previous
#include <cuda_runtime.h>
#include <stdint.h>

// Problem constants (verified by round-5 diagnostics)
#define K_F      1024
#define N_ROWS   256          // B*S = 4*64
#define DIM      256
#define F_FACTS  1000000
#define TOPK     128
#define NEG_INFF (-1.0e9f)

// Inputs: 0=fact_success(int32 bool), 1=fact_item_idx(int32),
// 2=facts_idx(int32 [F,3]), 3=entity_emb(f32), 4=rel_emb(f32), 5=top_k(=128)
// Output: float32 0.0/1.0 mask [256,1024]  (verified in round 7)

__device__ float g_scores[N_ROWS * K_F];

// ---------------------------------------------------------------------------
// Kernel 1 (UNCHANGED — verified passing): one warp per fact. Terms bit-match
// the reference (fl32(fl32(s*r)*o), no FMA); exact double accumulation.
// ---------------------------------------------------------------------------
__global__ void __launch_bounds__(256)
score_kernel(const int*   __restrict__ success,
             const int*   __restrict__ item_idx,
             const int*   __restrict__ facts_idx,
             const float* __restrict__ ent,
             const float* __restrict__ rel)
{
    int gw   = (blockIdx.x * blockDim.x + threadIdx.x) >> 5;  // fact id
    int lane = threadIdx.x & 31;
    if (gw >= N_ROWS * K_F) return;
    if (!success[gw]) return;   // warp-uniform

    int fidx = item_idx[gw];
    fidx = min(max(fidx, 0), F_FACTS - 1);

    int t = 0;
    if (lane < 3) t = facts_idx[fidx * 3 + lane];
    int s_i = __shfl_sync(0xffffffffu, t, 0);
    int r_i = __shfl_sync(0xffffffffu, t, 1);
    int o_i = __shfl_sync(0xffffffffu, t, 2);

    const float4* sp = (const float4*)(ent + (size_t)s_i * DIM);
    const float4* rp = (const float4*)(rel + (size_t)r_i * DIM);
    const float4* op = (const float4*)(ent + (size_t)o_i * DIM);

    double acc = 0.0;
#pragma unroll
    for (int i = 0; i < 2; ++i) {
        float4 a = __ldg(&sp[lane + 32 * i]);
        float4 b = __ldg(&rp[lane + 32 * i]);
        float4 c = __ldg(&op[lane + 32 * i]);
        acc += (double)__fmul_rn(__fmul_rn(a.x, b.x), c.x);
        acc += (double)__fmul_rn(__fmul_rn(a.y, b.y), c.y);
        acc += (double)__fmul_rn(__fmul_rn(a.z, b.z), c.z);
        acc += (double)__fmul_rn(__fmul_rn(a.w, b.w), c.w);
    }
#pragma unroll
    for (int off = 16; off; off >>= 1)
        acc += __shfl_down_sync(0xffffffffu, acc, off);

    if (lane == 0) g_scores[gw] = (float)acc;
}

// Order-preserving float -> uint key (larger float => larger uint)
__device__ __forceinline__ unsigned orderKey(float f) {
    unsigned u = __float_as_uint(f);
    return (u & 0x80000000u) ? ~u : (u | 0x80000000u);
}

// ---------------------------------------------------------------------------
// Kernel 2 (REWRITTEN): byte-wise radix select, 4 passes, warp-level suffix
// scan. 16 __syncthreads total (was 96). Exact jax.lax.top_k tie semantics.
// ---------------------------------------------------------------------------
__global__ void __launch_bounds__(256)
topk_kernel(const int* __restrict__ success,
            float*     __restrict__ out)
{
    __shared__ unsigned keys[K_F];
    __shared__ int hist[256];
    __shared__ int warpsum[8];
    __shared__ int s_digit, s_rem, s_eq;

    const int row  = blockIdx.x;
    const int tid  = threadIdx.x;
    const int lane = tid & 31;
    const int w    = tid >> 5;
    const float* rs = g_scores + row * K_F;
    const int*   su = success  + row * K_F;

    int      myS[4];
    unsigned myK[4];
#pragma unroll
    for (int i = 0; i < 4; ++i) {
        int j = tid + 256 * i;
        int s = su[j];
        myS[i] = s;
        float f = s ? rs[j] : NEG_INFF;
        myK[i] = orderKey(f);
        keys[j] = myK[i];
    }

    unsigned prefix = 0;      // decided high bits
    int remaining = TOPK;
#pragma unroll
    for (int shift = 24; shift >= 0; shift -= 8) {
        hist[tid] = 0;
        __syncthreads();                               // sync1: hist cleared (also covers keys[] on first pass)

        const unsigned hi_mask = (shift == 24) ? 0u : (0xFFFFFFFFu << (shift + 8));
#pragma unroll
        for (int i = 0; i < 4; ++i) {
            unsigned k = myK[i];
            if ((k & hi_mask) == prefix)
                atomicAdd(&hist[(k >> shift) & 0xFFu], 1);
        }
        __syncthreads();                               // sync2: histogram built

        // Suffix sum S[t] = sum_{d>=t} hist[d]; warp-level, no barriers.
        const int h = hist[tid];
        int v = h;
#pragma unroll
        for (int off = 1; off < 32; off <<= 1) {
            int n = __shfl_down_sync(0xffffffffu, v, off);
            if (lane + off < 32) v += n;
        }
        if (lane == 0) warpsum[w] = v;                 // warp-local suffix total
        __syncthreads();                               // sync3: warpsums ready

        int above = 0;
#pragma unroll
        for (int w2 = 0; w2 < 8; ++w2)
            if (w2 > w) above += warpsum[w2];
        const int S = v + above;                       // count(digit >= tid) among matching

        // Unique thread: bucket where the cumulative (from top) crosses remaining.
        if (S >= remaining && S - h < remaining) {
            s_digit = tid;
            s_rem   = remaining - (S - h);             // slots left inside this bucket
            s_eq    = h;                               // bucket population
        }
        __syncthreads();                               // sync4: selection published

        prefix |= ((unsigned)s_digit) << shift;
        remaining = s_rem;
        // next pass's sync1+sync2 precede any rewrite of s_digit/s_rem — safe.
    }

    const unsigned T  = prefix;        // exact value of the TOPK-th largest key
    const int      R  = remaining;     // ties at T that survive (lowest index first)
    const int      EQ = s_eq;          // total keys == T

#pragma unroll
    for (int i = 0; i < 4; ++i) {
        int j = tid + 256 * i;
        bool keep;
        if (myK[i] > T) {
            keep = true;
        } else if (myK[i] == T) {
            if (R == EQ) {
                keep = true;                           // all ties fit — common case
            } else {
                int before = 0;                        // rare: duplicate-score boundary
                for (int j2 = 0; j2 < j; ++j2) before += (keys[j2] == T);
                keep = (before < R);
            }
        } else {
            keep = false;
        }
        out[row * K_F + j] = (myS[i] && keep) ? 1.0f : 0.0f;
    }
}

// ---------------------------------------------------------------------------
extern "C" void kernel_launch(void* const* d_in, const int* in_sizes, int n_in,
                              void* d_out, int out_size)
{
    const int*   success   = (const int*)  d_in[0];
    const int*   item_idx  = (const int*)  d_in[1];
    const int*   facts_idx = (const int*)  d_in[2];
    const float* ent       = (const float*)d_in[3];
    const float* rel       = (const float*)d_in[4];
    (void)in_sizes; (void)n_in; (void)out_size;   // top_k verified = 128

    score_kernel<<<(N_ROWS * K_F) / 8, 256>>>(success, item_idx, facts_idx, ent, rel);
    topk_kernel<<<N_ROWS, 256>>>(success, (float*)d_out);
}